// round 11
// baseline (speedup 1.0000x reference)
#include <cuda_runtime.h>
#include <cstdint>

#define THREADS 256
#define KDIM 120
#define INP 512
#define NPAIR 13
#define KC 24
#define NCHUNK 5
#define NJ2 12
#define KSTRIDE 514                          // floats per k-row (even -> 8B-aligned LDS.64)

#define PLANE (KC * KSTRIDE)                 // 12336 floats per buffer
#define SCR_STRIDE 27                        // routing scratch aliases buffer 0
#define RED_OFF (2 * PLANE)                  // 24672
#define RAW_OFF (RED_OFF + 8 * 26)
#define OUT_OFF (RAW_OFF + 32)
#define SMEM_FLOATS (OUT_OFF + 32)           // 24944
#define SMEM_BYTES (SMEM_FLOATS * 4)         // 99776

typedef unsigned long long ull;

// W packed [120][26] floats (col 25 = 0): 780 ulonglong2.
// j2-block g: cW2[g*13+q]; q=0..5: k0 pairs (2q,2q+1); q=6: {k0 pair12, k1 pair0};
// q=7..12: k1 pairs (2q-13, 2q-12).
__constant__ ulonglong2 cW2[780];            // zero-init; pad lanes never written

__device__ __forceinline__ ull dup2(float v) {
    ull r;
    asm("mov.b64 %0, {%1, %1};" : "=l"(r) : "r"(__float_as_uint(v)));
    return r;
}
__device__ __forceinline__ void ffma2(ull& d, ull a, ull b) {
    asm("fma.rn.f32x2 %0, %1, %2, %0;" : "+l"(d) : "l"(a), "l"(b));
}
__device__ __forceinline__ void unpack2(ull v, float& lo, float& hi) {
    unsigned int a, b2;
    asm("mov.b64 {%0, %1}, %2;" : "=r"(a), "=r"(b2) : "l"(v));
    lo = __uint_as_float(a);
    hi = __uint_as_float(b2);
}
__device__ __forceinline__ uint32_t smem_u32(const void* p) {
    uint32_t a;
    asm("{ .reg .u64 t; cvta.to.shared.u64 t, %1; cvt.u32.u64 %0, t; }" : "=r"(a) : "l"(p));
    return a;
}
__device__ __forceinline__ void cpasync4(uint32_t dst, const float* src) {
    asm volatile("cp.async.ca.shared.global [%0], [%1], 4;" :: "r"(dst), "l"(src) : "memory");
}
__device__ __forceinline__ void cp_commit() {
    asm volatile("cp.async.commit_group;" ::: "memory");
}
template <int N>
__device__ __forceinline__ void cp_wait() {
    asm volatile("cp.async.wait_group %0;" :: "n"(N) : "memory");
}

extern __shared__ float smem[];

__global__ void __launch_bounds__(THREADS, 2)
caps_kernel(const float* __restrict__ x, float* __restrict__ out)
{
    const int b = blockIdx.x;
    const int t = threadIdx.x;
    const int lane = t & 31, g = t >> 5;

    float* scratch = smem;                 // routing partials alias buffers
    float* red     = smem + RED_OFF;       // [8][26]
    float* raw     = smem + RAW_OFF;       // [25]
    float* sOut    = smem + OUT_OFF;       // [25]

    const float* xb = x + (size_t)b * (INP * KDIM);
    const uint32_t smb = smem_u32(smem);

    // staging decomposition: element e = t + i*256, i = 3a+bb (a<16, bb<3);
    // 768 = 24*32 exactly -> row(e) = row_b(bb) + 32a, kk(e) = kk_b(bb).
    int row_b[3], kk_b[3];
    #pragma unroll
    for (int bb = 0; bb < 3; bb++) {
        int e = t + bb * THREADS;
        row_b[bb] = e / KC;
        kk_b[bb]  = e % KC;
    }

    // issue all 48 4B cp.asyncs for chunk kc into buffer buf
    auto issue_chunk = [&](int kc, int buf) {
        const float* src0 = xb + kc * KC;
        uint32_t dst0 = smb + (uint32_t)buf * (PLANE * 4);
        #pragma unroll
        for (int bb = 0; bb < 3; bb++) {
            const float* sp = src0 + (size_t)row_b[bb] * KDIM + kk_b[bb];
            uint32_t dp = dst0 + (uint32_t)(kk_b[bb] * KSTRIDE + row_b[bb]) * 4;
            #pragma unroll
            for (int a = 0; a < 16; a++)
                cpasync4(dp + a * 128u, sp + a * (32 * KDIM));
        }
    };

    // ---- GEMM: u_hat[2 rows][26 cols] in 26 f32x2 accumulators, W from constant ----
    ull acc[2][NPAIR];
    #pragma unroll
    for (int r = 0; r < 2; r++)
        #pragma unroll
        for (int p = 0; p < NPAIR; p++) acc[r][p] = 0ull;

    issue_chunk(0, 0);
    cp_commit();

    for (int kc = 0; kc < NCHUNK; kc++) {
        const int buf = kc & 1;
        if (kc + 1 < NCHUNK) {
            issue_chunk(kc + 1, buf ^ 1);
            cp_commit();
            cp_wait<1>();          // chunk kc complete
        } else {
            cp_wait<0>();
        }
        __syncthreads();

        const float* cur = smem + buf * PLANE;
        const ulonglong2* wb = cW2 + kc * NJ2 * NPAIR;
        #pragma unroll
        for (int j2 = 0; j2 < NJ2; j2++) {
            // sX[k][row]: xa = {x(k0,r0), x(k0,r1)}, xbv = {x(k1,r0), x(k1,r1)}
            float2 xa  = *reinterpret_cast<const float2*>(cur + (2 * j2) * KSTRIDE + 2 * t);
            float2 xbv = *reinterpret_cast<const float2*>(cur + (2 * j2 + 1) * KSTRIDE + 2 * t);
            ull a0 = dup2(xa.x);    // k0, row0
            ull b0 = dup2(xa.y);    // k0, row1
            ull a1 = dup2(xbv.x);   // k1, row0
            ull b1 = dup2(xbv.y);   // k1, row1

            const ulonglong2* wq = wb + j2 * NPAIR;
            #pragma unroll
            for (int q = 0; q < 6; q++) {
                ulonglong2 v = wq[q];
                ffma2(acc[0][2 * q],     a0, v.x);
                ffma2(acc[1][2 * q],     b0, v.x);
                ffma2(acc[0][2 * q + 1], a0, v.y);
                ffma2(acc[1][2 * q + 1], b0, v.y);
            }
            {
                ulonglong2 v = wq[6];
                ffma2(acc[0][12], a0, v.x);
                ffma2(acc[1][12], b0, v.x);
                ffma2(acc[0][0],  a1, v.y);
                ffma2(acc[1][0],  b1, v.y);
            }
            #pragma unroll
            for (int q = 7; q < 13; q++) {
                ulonglong2 v = wq[q];
                ffma2(acc[0][2 * q - 13], a1, v.x);
                ffma2(acc[1][2 * q - 13], b1, v.x);
                ffma2(acc[0][2 * q - 12], a1, v.y);
                ffma2(acc[1][2 * q - 12], b1, v.y);
            }
        }
        __syncthreads();           // all reads of buf done before it is refilled
    }

    // ---- unpack u_hat ----
    float u[2][26];
    #pragma unroll
    for (int r = 0; r < 2; r++)
        #pragma unroll
        for (int p = 0; p < NPAIR; p++)
            unpack2(acc[r][p], u[r][2 * p], u[r][2 * p + 1]);

    float bb2[2][5];
    #pragma unroll
    for (int r = 0; r < 2; r++)
        #pragma unroll
        for (int i = 0; i < 5; i++) bb2[r][i] = 0.f;

    // ---- 4 routing iterations (verbatim from validated kernel) ----
    for (int it = 0; it < 4; it++) {
        float cw[2][5];
        #pragma unroll
        for (int r = 0; r < 2; r++) {
            float m = bb2[r][0];
            #pragma unroll
            for (int i = 1; i < 5; i++) m = fmaxf(m, bb2[r][i]);
            float e[5], s = 0.f;
            #pragma unroll
            for (int i = 0; i < 5; i++) { e[i] = __expf(bb2[r][i] - m); s += e[i]; }
            float inv = 1.f / s;
            #pragma unroll
            for (int i = 0; i < 5; i++) cw[r][i] = e[i] * inv;
        }
        #pragma unroll
        for (int c = 0; c < 25; c++)
            scratch[t * SCR_STRIDE + c] = cw[0][c / 5] * u[0][c] + cw[1][c / 5] * u[1][c];
        __syncthreads();
        if (lane < 25) {
            float s = 0.f;
            #pragma unroll
            for (int uu = 0; uu < 32; uu++) s += scratch[(g * 32 + uu) * SCR_STRIDE + lane];
            red[g * 26 + lane] = s;
        }
        __syncthreads();
        if (t < 25) {
            float s = 0.f;
            #pragma unroll
            for (int gg = 0; gg < 8; gg++) s += red[gg * 26 + t];
            raw[t] = s;
        }
        __syncthreads();
        if (t < 25) {
            int i5 = (t / 5) * 5;
            float sq = 0.f;
            #pragma unroll
            for (int k = 0; k < 5; k++) { float v = raw[i5 + k]; sq += v * v; }
            sOut[t] = raw[t] * rsqrtf(sq + 1e-7f);   // squash = pure norm-normalization
        }
        __syncthreads();
        if (it < 3) {
            float ov[25];
            #pragma unroll
            for (int c = 0; c < 25; c++) ov[c] = sOut[c];
            #pragma unroll
            for (int r = 0; r < 2; r++)
                #pragma unroll
                for (int i = 0; i < 5; i++) {
                    float s = 0.f;
                    #pragma unroll
                    for (int k = 0; k < 5; k++) s += ov[i * 5 + k] * u[r][i * 5 + k];
                    bb2[r][i] = s;   // b REPLACED each iteration (matches reference)
                }
        }
    }

    if (t < 25) out[b * 25 + t] = sOut[t];
}

extern "C" void kernel_launch(void* const* d_in, const int* in_sizes, int n_in,
                              void* d_out, int out_size)
{
    const float* x = (const float*)d_in[0];
    const float* W = (const float*)d_in[1];
    float* out = (float*)d_out;

    // Pack W[120][25] -> constant [120][26] floats (col 25 stays 0 from static init).
    void* csym = nullptr;
    cudaGetSymbolAddress(&csym, cW2);
    cudaMemcpy2DAsync(csym, 26 * sizeof(float),
                      W, 25 * sizeof(float),
                      25 * sizeof(float), KDIM,
                      cudaMemcpyDeviceToDevice, 0);

    cudaFuncSetAttribute(caps_kernel, cudaFuncAttributeMaxDynamicSharedMemorySize, SMEM_BYTES);
    caps_kernel<<<1024, THREADS, SMEM_BYTES>>>(x, out);
}